// round 7
// baseline (speedup 1.0000x reference)
#include <cuda_runtime.h>
#include <math.h>

// FFM forward: B=16384, LATENT=16, F=6 fields.
// DIMS     = {1000000, 500000, 500000, 100000, 10000, 1000}
// SEQ_LENS = [1, 1, 50, 20, 1, 1]
//
// Round 6: E2 token-range segmentation with smem COMPACTION (full load
// density, no predicated dead iterations), E3 means overlapped into pass 1
// as extra blocks (L2-request-bound work hides under E2's DRAM-bound work).

#define B_TOTAL 16384
#define LAT     16
#define M_SPLIT 250000

__device__ float g_M2[(size_t)B_TOTAL * 5 * LAT];   // 5.24 MB scratch
__device__ float g_M3[(size_t)B_TOTAL * 5 * LAT];   // 5.24 MB scratch

// ---------------------------------------------------------------------------
// E2 segment body: compact this segment's tokens in smem, then gather with
// 8-wide unroll (all loads useful). Thread = (lane, slot, elem); 4 elems/blk.
// ---------------------------------------------------------------------------
template<int SEG, bool FIRST>
__device__ __forceinline__ void e2_seg_body(const int* __restrict__ x2,
                                            const float* __restrict__ E2,
                                            int blk)
{
    __shared__ int raw[4][50];
    __shared__ int cmp[4][50];
    __shared__ int cnt[4];

    const int tid = threadIdx.x;
    const int b0  = blk * 4;

    for (int i = tid; i < 200; i += 320)
        raw[i / 50][i % 50] = x2[(size_t)b0 * 50 + i];
    __syncthreads();

    if (tid < 4) {                       // one partitioner per element
        int c = 0;
#pragma unroll 1
        for (int t = 0; t < 50; ++t) {
            const int tok = raw[tid][t];
            const bool in = SEG ? (tok >= M_SPLIT) : (tok < M_SPLIT);
            if (in) cmp[tid][c++] = tok;
        }
        cnt[tid] = c;
    }
    __syncthreads();

    const int lane = tid & 15;
    const int sy   = (tid >> 4) % 5;
    const int z    = tid / 80;
    const float* base = E2 + (size_t)sy * 500000 * LAT + lane;
    const int n = cnt[z];

    float p0=0.f,p1=0.f,p2=0.f,p3=0.f,p4=0.f,p5=0.f,p6=0.f,p7=0.f;
    int t = 0;
#pragma unroll 1
    for (; t + 8 <= n; t += 8) {         // 8 independent loads in flight
        p0 += __ldg(base + (size_t)cmp[z][t    ] * LAT);
        p1 += __ldg(base + (size_t)cmp[z][t + 1] * LAT);
        p2 += __ldg(base + (size_t)cmp[z][t + 2] * LAT);
        p3 += __ldg(base + (size_t)cmp[z][t + 3] * LAT);
        p4 += __ldg(base + (size_t)cmp[z][t + 4] * LAT);
        p5 += __ldg(base + (size_t)cmp[z][t + 5] * LAT);
        p6 += __ldg(base + (size_t)cmp[z][t + 6] * LAT);
        p7 += __ldg(base + (size_t)cmp[z][t + 7] * LAT);
    }
#pragma unroll 1
    for (; t < n; ++t)
        p0 += __ldg(base + (size_t)cmp[z][t] * LAT);

    const float s = ((p0 + p1) + (p2 + p3)) + ((p4 + p5) + (p6 + p7));

    float* dst = &g_M2[((size_t)(b0 + z) * 5 + sy) * LAT + lane];
    if (FIRST) *dst = s;                                  // raw partial sum
    else       *dst = (*dst + s) * (1.0f / 50.0f);        // finish mean
}

// ---------------------------------------------------------------------------
// E3 mean body: table is 32MB (L2-resident); 4 elems/block, 20 loads/thread.
// ---------------------------------------------------------------------------
__device__ __forceinline__ void e3_body(const int* __restrict__ x3,
                                        const float* __restrict__ E3,
                                        int blk)
{
    __shared__ int tk3[4][20];
    const int tid = threadIdx.x;
    const int b0  = blk * 4;

    if (tid < 80) tk3[tid / 20][tid % 20] = x3[(size_t)b0 * 20 + tid];
    __syncthreads();

    const int lane = tid & 15;
    const int sy   = (tid >> 4) % 5;
    const int z    = tid / 80;
    const float* base = E3 + (size_t)sy * 100000 * LAT + lane;

    float p0=0.f,p1=0.f,p2=0.f,p3=0.f;
#pragma unroll
    for (int t = 0; t < 20; t += 4) {
        p0 += __ldg(base + (size_t)tk3[z][t    ] * LAT);
        p1 += __ldg(base + (size_t)tk3[z][t + 1] * LAT);
        p2 += __ldg(base + (size_t)tk3[z][t + 2] * LAT);
        p3 += __ldg(base + (size_t)tk3[z][t + 3] * LAT);
    }
    g_M3[((size_t)(b0 + z) * 5 + sy) * LAT + lane] =
        ((p0 + p1) + (p2 + p3)) * (1.0f / 20.0f);
}

// ---------------------------------------------------------------------------
// Pass 1: blocks [0,4096) = E2 segment 0;  blocks [4096,8192) = E3 means.
// Pass 2: E2 segment 1 (accumulates into g_M2, finishes the mean).
// ---------------------------------------------------------------------------
__global__ __launch_bounds__(320) void p1_kernel(
    const int* __restrict__ x2, const float* __restrict__ E2,
    const int* __restrict__ x3, const float* __restrict__ E3)
{
    if (blockIdx.x < 4096) e2_seg_body<0, true>(x2, E2, blockIdx.x);
    else                   e3_body(x3, E3, blockIdx.x - 4096);
}

__global__ __launch_bounds__(320) void p2_kernel(
    const int* __restrict__ x2, const float* __restrict__ E2)
{
    e2_seg_body<1, false>(x2, E2, blockIdx.x);
}

// ---------------------------------------------------------------------------
// Final kernel: fields 0,1,4,5 + L gathers + scratch reads + epilogue.
// 16 lanes per element; 256 threads = 16 elements.
// ---------------------------------------------------------------------------
__global__ __launch_bounds__(256) void final_kernel(
    const int* __restrict__ x0, const int* __restrict__ x1, const int* __restrict__ x2,
    const int* __restrict__ x3, const int* __restrict__ x4, const int* __restrict__ x5,
    const float* __restrict__ E0, const float* __restrict__ E1,
    const float* __restrict__ E4, const float* __restrict__ E5,
    const float* __restrict__ L0, const float* __restrict__ L1, const float* __restrict__ L2,
    const float* __restrict__ L3, const float* __restrict__ L4, const float* __restrict__ L5,
    const float* __restrict__ Wd, const float* __restrict__ bd,
    float* __restrict__ out)
{
    __shared__ int tk[16][74];   // [elem][f0|f1|f2*50|f3*20|f4|f5]

    const int tid = threadIdx.x;
    const int b0  = blockIdx.x * 16;

    for (int i = tid; i < 16 * 74; i += 256) {
        const int e = i / 74, o = i % 74;
        const int b = b0 + e;
        int v;
        if      (o == 0)  v = x0[b];
        else if (o == 1)  v = x1[b];
        else if (o < 52)  v = x2[(size_t)b * 50 + (o - 2)];
        else if (o < 72)  v = x3[(size_t)b * 20 + (o - 52)];
        else if (o == 72) v = x4[b];
        else              v = x5[b];
        tk[e][o] = v;
    }
    __syncthreads();

    const int lane = tid & 15;
    const int z    = tid >> 4;
    const int b    = b0 + z;

    const float w0 = __ldg(Wd + 0);
    const float w1 = __ldg(Wd + 1);
    const float w2 = __ldg(Wd + 2) * (1.0f / 50.0f);
    const float w3 = __ldg(Wd + 3) * (1.0f / 20.0f);
    const float w4 = __ldg(Wd + 4);
    const float w5 = __ldg(Wd + 5);

    const int t0 = tk[z][0], t1 = tk[z][1], t4 = tk[z][72], t5 = tk[z][73];
    float a0[5], a1[5], a4[5], a5[5], m2[5], m3[5];
#pragma unroll
    for (int s = 0; s < 5; ++s) {
        a0[s] = __ldg(E0 + ((size_t)s * 1000000 + t0) * LAT + lane);
        a1[s] = __ldg(E1 + ((size_t)s *  500000 + t1) * LAT + lane);
        a4[s] = __ldg(E4 + ((size_t)s *   10000 + t4) * LAT + lane);
        a5[s] = __ldg(E5 + ((size_t)s *    1000 + t5) * LAT + lane);
        m2[s] = g_M2[((size_t)b * 5 + s) * LAT + lane];
        m3[s] = g_M3[((size_t)b * 5 + s) * LAT + lane];
    }

    // linear term: gathered once per 16-lane group (warp broadcast)
    float lp[4];
    lp[0] = __ldg(L0 + t0) * w0;
    lp[1] = __ldg(L1 + t1) * w1;
    lp[2] = __ldg(L4 + t4) * w4;
    lp[3] = __ldg(L5 + t5) * w5;
#pragma unroll
    for (int t = 0; t < 50; ++t) lp[t & 3] += __ldg(L2 + tk[z][2 + t]) * w2;
#pragma unroll
    for (int t = 0; t < 20; ++t) lp[t & 3] += __ldg(L3 + tk[z][52 + t]) * w3;
    const float lin = (lp[0] + lp[1]) + (lp[2] + lp[3]);

    // fm = sum over pairs (i<j): a_i[slot j-1] * a_j[slot i]
    float fm = 0.f;
    fm += a0[0]*a1[0];   // (0,1)
    fm += a0[1]*m2[0];   // (0,2)
    fm += a0[2]*m3[0];   // (0,3)
    fm += a0[3]*a4[0];   // (0,4)
    fm += a0[4]*a5[0];   // (0,5)
    fm += a1[1]*m2[1];   // (1,2)
    fm += a1[2]*m3[1];   // (1,3)
    fm += a1[3]*a4[1];   // (1,4)
    fm += a1[4]*a5[1];   // (1,5)
    fm += m2[2]*m3[2];   // (2,3)
    fm += m2[3]*a4[2];   // (2,4)
    fm += m2[4]*a5[2];   // (2,5)
    fm += m3[3]*a4[3];   // (3,4)
    fm += m3[4]*a5[3];   // (3,5)
    fm += a4[4]*a5[4];   // (4,5)

    fm += __shfl_xor_sync(0xffffffffu, fm, 8, 16);
    fm += __shfl_xor_sync(0xffffffffu, fm, 4, 16);
    fm += __shfl_xor_sync(0xffffffffu, fm, 2, 16);
    fm += __shfl_xor_sync(0xffffffffu, fm, 1, 16);

    if (lane == 0) {
        float v = lin + __ldg(bd);
        v = v > 0.f ? v : 0.f;      // relu
        v += fm;
        out[b] = 1.0f / (1.0f + expf(-v));
    }
}

extern "C" void kernel_launch(void* const* d_in, const int* in_sizes, int n_in,
                              void* d_out, int out_size)
{
    static const long DIMS[6] = {1000000, 500000, 500000, 100000, 10000, 1000};

    const int*   x[6];
    const float* E[6];
    const float* L[6];

    for (int i = 0; i < 6; ++i) x[i] = (const int*)d_in[i];

    // Inputs 6..17 are E and L tables in field order; disambiguate by size:
    // E_i has 80*DIMS[i] elements, L_i has DIMS[i]. Disjoint sets.
    int ei = 0, li = 0;
    for (int i = 6; i < 18 && i < n_in; ++i) {
        long sz = (long)in_sizes[i];
        if (ei < 6 && sz == 80L * DIMS[ei]) {
            E[ei++] = (const float*)d_in[i];
        } else {
            L[li++] = (const float*)d_in[i];
        }
    }

    const float* Wd = (const float*)d_in[18];
    const float* bd = (const float*)d_in[19];

    // Pass 1: E2 segment 0 (compacted) + E3 means (overlapped blocks).
    p1_kernel<<<8192, 320>>>(x[2], E[2], x[3], E[3]);
    // Pass 2: E2 segment 1, finishes g_M2 means.
    p2_kernel<<<4096, 320>>>(x[2], E[2]);
    // Final: cheap fields + linear + epilogue.
    final_kernel<<<B_TOTAL / 16, 256>>>(
        x[0], x[1], x[2], x[3], x[4], x[5],
        E[0], E[1], E[4], E[5],
        L[0], L[1], L[2], L[3], L[4], L[5],
        Wd, bd, (float*)d_out);
}

// round 9
// speedup vs baseline: 1.0620x; 1.0620x over previous
#include <cuda_runtime.h>
#include <math.h>

// FFM forward: B=16384, LATENT=16, F=6 fields.
// DIMS     = {1000000, 500000, 500000, 100000, 10000, 1000}
// SEQ_LENS = [1, 1, 50, 20, 1, 1]
//
// Round 7: E2 token-range segmentation executed at full static MLP.
// Each seg-pass thread owns TWO batch elements -> 100 compile-time-unrolled
// predicated loads (~50 useful) = the load shape that measured 68.6% DRAM
// duty in round 4. E3 kernel gets the same 2-elem treatment (40 static
// loads). Sequential: seg0 -> seg1 -> e3 -> final.

#define B_TOTAL 16384
#define LAT     16
#define M_SPLIT 250000

__device__ float g_M2[(size_t)B_TOTAL * 5 * LAT];   // 5.24 MB scratch
__device__ float g_M3[(size_t)B_TOTAL * 5 * LAT];   // 5.24 MB scratch

// ---------------------------------------------------------------------------
// E2 segment pass: thread = (lane, slot, elem-pair). 320 threads = 8 elems.
// Fully unrolled 2x50 predicated loads; predicate uniform per 16-lane group.
// ---------------------------------------------------------------------------
template<int LO, int HI, bool FIRST>
__global__ __launch_bounds__(320) void e2_seg_kernel(const int* __restrict__ x2,
                                                     const float* __restrict__ E2)
{
    __shared__ int tk[8][50];

    const int tid = threadIdx.x;
    const int b0  = blockIdx.x * 8;

    for (int i = tid; i < 400; i += 320)
        tk[i / 50][i % 50] = x2[(size_t)b0 * 50 + i];
    __syncthreads();

    const int lane = tid & 15;
    const int sy   = (tid >> 4) % 5;
    const int z    = tid / 80;            // elem pair 0..3
    const int eA   = 2 * z, eB = 2 * z + 1;

    const float* base = E2 + (size_t)sy * 500000 * LAT + lane;

    float pa0=0.f,pa1=0.f,pa2=0.f,pa3=0.f;
    float pb0=0.f,pb1=0.f,pb2=0.f,pb3=0.f;

#pragma unroll
    for (int t = 0; t < 50; t += 4) {
        const int a0 = tk[eA][t], a1 = tk[eA][t+1], a2 = tk[eA][t+2], a3 = tk[eA][t+3];
        const int c0 = tk[eB][t], c1 = tk[eB][t+1], c2 = tk[eB][t+2], c3 = tk[eB][t+3];
        if (a0 >= LO && a0 < HI) pa0 += __ldg(base + (size_t)a0 * LAT);
        if (a1 >= LO && a1 < HI) pa1 += __ldg(base + (size_t)a1 * LAT);
        if (a2 >= LO && a2 < HI) pa2 += __ldg(base + (size_t)a2 * LAT);
        if (a3 >= LO && a3 < HI) pa3 += __ldg(base + (size_t)a3 * LAT);
        if (c0 >= LO && c0 < HI) pb0 += __ldg(base + (size_t)c0 * LAT);
        if (c1 >= LO && c1 < HI) pb1 += __ldg(base + (size_t)c1 * LAT);
        if (c2 >= LO && c2 < HI) pb2 += __ldg(base + (size_t)c2 * LAT);
        if (c3 >= LO && c3 < HI) pb3 += __ldg(base + (size_t)c3 * LAT);
    }

    const float sA = (pa0 + pa1) + (pa2 + pa3);
    const float sB = (pb0 + pb1) + (pb2 + pb3);

    float* dA = &g_M2[((size_t)(b0 + eA) * 5 + sy) * LAT + lane];
    float* dB = &g_M2[((size_t)(b0 + eB) * 5 + sy) * LAT + lane];
    if (FIRST) {
        *dA = sA;
        *dB = sB;
    } else {
        *dA = (*dA + sA) * (1.0f / 50.0f);
        *dB = (*dB + sB) * (1.0f / 50.0f);
    }
}

// ---------------------------------------------------------------------------
// E3 means: table = 32MB (L2-resident after first touch). 2 elems/thread,
// 40 fully unrolled loads. 320 threads = 8 elems/block.
// ---------------------------------------------------------------------------
__global__ __launch_bounds__(320) void e3_kernel(const int* __restrict__ x3,
                                                 const float* __restrict__ E3)
{
    __shared__ int tk[8][20];

    const int tid = threadIdx.x;
    const int b0  = blockIdx.x * 8;

    if (tid < 160) tk[tid / 20][tid % 20] = x3[(size_t)b0 * 20 + tid];
    __syncthreads();

    const int lane = tid & 15;
    const int sy   = (tid >> 4) % 5;
    const int z    = tid / 80;
    const int eA   = 2 * z, eB = 2 * z + 1;

    const float* base = E3 + (size_t)sy * 100000 * LAT + lane;

    float pa0=0.f,pa1=0.f,pa2=0.f,pa3=0.f;
    float pb0=0.f,pb1=0.f,pb2=0.f,pb3=0.f;
#pragma unroll
    for (int t = 0; t < 20; t += 4) {
        pa0 += __ldg(base + (size_t)tk[eA][t    ] * LAT);
        pa1 += __ldg(base + (size_t)tk[eA][t + 1] * LAT);
        pa2 += __ldg(base + (size_t)tk[eA][t + 2] * LAT);
        pa3 += __ldg(base + (size_t)tk[eA][t + 3] * LAT);
        pb0 += __ldg(base + (size_t)tk[eB][t    ] * LAT);
        pb1 += __ldg(base + (size_t)tk[eB][t + 1] * LAT);
        pb2 += __ldg(base + (size_t)tk[eB][t + 2] * LAT);
        pb3 += __ldg(base + (size_t)tk[eB][t + 3] * LAT);
    }
    g_M3[((size_t)(b0 + eA) * 5 + sy) * LAT + lane] =
        ((pa0 + pa1) + (pa2 + pa3)) * (1.0f / 20.0f);
    g_M3[((size_t)(b0 + eB) * 5 + sy) * LAT + lane] =
        ((pb0 + pb1) + (pb2 + pb3)) * (1.0f / 20.0f);
}

// ---------------------------------------------------------------------------
// Final kernel: fields 0,1,4,5 + L gathers (8 partials) + scratch + epilogue.
// 16 lanes per element; 256 threads = 16 elements.
// ---------------------------------------------------------------------------
__global__ __launch_bounds__(256) void final_kernel(
    const int* __restrict__ x0, const int* __restrict__ x1, const int* __restrict__ x2,
    const int* __restrict__ x3, const int* __restrict__ x4, const int* __restrict__ x5,
    const float* __restrict__ E0, const float* __restrict__ E1,
    const float* __restrict__ E4, const float* __restrict__ E5,
    const float* __restrict__ L0, const float* __restrict__ L1, const float* __restrict__ L2,
    const float* __restrict__ L3, const float* __restrict__ L4, const float* __restrict__ L5,
    const float* __restrict__ Wd, const float* __restrict__ bd,
    float* __restrict__ out)
{
    __shared__ int tk[16][74];   // [elem][f0|f1|f2*50|f3*20|f4|f5]

    const int tid = threadIdx.x;
    const int b0  = blockIdx.x * 16;

    for (int i = tid; i < 16 * 74; i += 256) {
        const int e = i / 74, o = i % 74;
        const int b = b0 + e;
        int v;
        if      (o == 0)  v = x0[b];
        else if (o == 1)  v = x1[b];
        else if (o < 52)  v = x2[(size_t)b * 50 + (o - 2)];
        else if (o < 72)  v = x3[(size_t)b * 20 + (o - 52)];
        else if (o == 72) v = x4[b];
        else              v = x5[b];
        tk[e][o] = v;
    }
    __syncthreads();

    const int lane = tid & 15;
    const int z    = tid >> 4;
    const int b    = b0 + z;

    const float w0 = __ldg(Wd + 0);
    const float w1 = __ldg(Wd + 1);
    const float w2 = __ldg(Wd + 2) * (1.0f / 50.0f);
    const float w3 = __ldg(Wd + 3) * (1.0f / 20.0f);
    const float w4 = __ldg(Wd + 4);
    const float w5 = __ldg(Wd + 5);

    const int t0 = tk[z][0], t1 = tk[z][1], t4 = tk[z][72], t5 = tk[z][73];
    float a0[5], a1[5], a4[5], a5[5], m2[5], m3[5];
#pragma unroll
    for (int s = 0; s < 5; ++s) {
        a0[s] = __ldg(E0 + ((size_t)s * 1000000 + t0) * LAT + lane);
        a1[s] = __ldg(E1 + ((size_t)s *  500000 + t1) * LAT + lane);
        a4[s] = __ldg(E4 + ((size_t)s *   10000 + t4) * LAT + lane);
        a5[s] = __ldg(E5 + ((size_t)s *    1000 + t5) * LAT + lane);
        m2[s] = g_M2[((size_t)b * 5 + s) * LAT + lane];
        m3[s] = g_M3[((size_t)b * 5 + s) * LAT + lane];
    }

    // linear term, 8 independent chains (gathered once per 16-lane group)
    float lp0 = __ldg(L0 + t0) * w0;
    float lp1 = __ldg(L1 + t1) * w1;
    float lp2 = __ldg(L4 + t4) * w4;
    float lp3 = __ldg(L5 + t5) * w5;
    float lp4 = 0.f, lp5 = 0.f, lp6 = 0.f, lp7 = 0.f;
#pragma unroll
    for (int t = 0; t < 48; t += 8) {
        lp0 += __ldg(L2 + tk[z][2 + t    ]) * w2;
        lp1 += __ldg(L2 + tk[z][2 + t + 1]) * w2;
        lp2 += __ldg(L2 + tk[z][2 + t + 2]) * w2;
        lp3 += __ldg(L2 + tk[z][2 + t + 3]) * w2;
        lp4 += __ldg(L2 + tk[z][2 + t + 4]) * w2;
        lp5 += __ldg(L2 + tk[z][2 + t + 5]) * w2;
        lp6 += __ldg(L2 + tk[z][2 + t + 6]) * w2;
        lp7 += __ldg(L2 + tk[z][2 + t + 7]) * w2;
    }
    lp0 += __ldg(L2 + tk[z][50]) * w2;
    lp1 += __ldg(L2 + tk[z][51]) * w2;
#pragma unroll
    for (int t = 0; t < 20; t += 4) {
        lp4 += __ldg(L3 + tk[z][52 + t    ]) * w3;
        lp5 += __ldg(L3 + tk[z][52 + t + 1]) * w3;
        lp6 += __ldg(L3 + tk[z][52 + t + 2]) * w3;
        lp7 += __ldg(L3 + tk[z][52 + t + 3]) * w3;
    }
    const float lin = ((lp0 + lp1) + (lp2 + lp3)) + ((lp4 + lp5) + (lp6 + lp7));

    // fm = sum over pairs (i<j): a_i[slot j-1] * a_j[slot i]
    float fm = 0.f;
    fm += a0[0]*a1[0];   // (0,1)
    fm += a0[1]*m2[0];   // (0,2)
    fm += a0[2]*m3[0];   // (0,3)
    fm += a0[3]*a4[0];   // (0,4)
    fm += a0[4]*a5[0];   // (0,5)
    fm += a1[1]*m2[1];   // (1,2)
    fm += a1[2]*m3[1];   // (1,3)
    fm += a1[3]*a4[1];   // (1,4)
    fm += a1[4]*a5[1];   // (1,5)
    fm += m2[2]*m3[2];   // (2,3)
    fm += m2[3]*a4[2];   // (2,4)
    fm += m2[4]*a5[2];   // (2,5)
    fm += m3[3]*a4[3];   // (3,4)
    fm += m3[4]*a5[3];   // (3,5)
    fm += a4[4]*a5[4];   // (4,5)

    fm += __shfl_xor_sync(0xffffffffu, fm, 8, 16);
    fm += __shfl_xor_sync(0xffffffffu, fm, 4, 16);
    fm += __shfl_xor_sync(0xffffffffu, fm, 2, 16);
    fm += __shfl_xor_sync(0xffffffffu, fm, 1, 16);

    if (lane == 0) {
        float v = lin + __ldg(bd);
        v = v > 0.f ? v : 0.f;      // relu
        v += fm;
        out[b] = 1.0f / (1.0f + expf(-v));
    }
}

extern "C" void kernel_launch(void* const* d_in, const int* in_sizes, int n_in,
                              void* d_out, int out_size)
{
    static const long DIMS[6] = {1000000, 500000, 500000, 100000, 10000, 1000};

    const int*   x[6];
    const float* E[6];
    const float* L[6];

    for (int i = 0; i < 6; ++i) x[i] = (const int*)d_in[i];

    // Inputs 6..17 are E and L tables in field order; disambiguate by size:
    // E_i has 80*DIMS[i] elements, L_i has DIMS[i]. Disjoint sets.
    int ei = 0, li = 0;
    for (int i = 6; i < 18 && i < n_in; ++i) {
        long sz = (long)in_sizes[i];
        if (ei < 6 && sz == 80L * DIMS[ei]) {
            E[ei++] = (const float*)d_in[i];
        } else {
            L[li++] = (const float*)d_in[i];
        }
    }

    const float* Wd = (const float*)d_in[18];
    const float* bd = (const float*)d_in[19];

    // E2 in two token-range segments, each with a 64.5MB L2-captured working
    // set, executed at full static MLP (100 predicated unrolled loads/thread).
    e2_seg_kernel<0,       M_SPLIT, true ><<<B_TOTAL / 8, 320>>>(x[2], E[2]);
    e2_seg_kernel<M_SPLIT, 500000,  false><<<B_TOTAL / 8, 320>>>(x[2], E[2]);
    // E3 means (table L2-resident), 40 static loads/thread.
    e3_kernel<<<B_TOTAL / 8, 320>>>(x[3], E[3]);
    // Cheap fields + linear + epilogue.
    final_kernel<<<B_TOTAL / 16, 256>>>(
        x[0], x[1], x[2], x[3], x[4], x[5],
        E[0], E[1], E[4], E[5],
        L[0], L[1], L[2], L[3], L[4], L[5],
        Wd, bd, (float*)d_out);
}

// round 10
// speedup vs baseline: 1.2830x; 1.2081x over previous
#include <cuda_runtime.h>
#include <math.h>

// FFM forward: B=16384, LATENT=16, F=6 fields.
// DIMS      = {1000000, 500000, 500000, 100000, 10000, 1000}
// SEQ_LENS  = [1, 1, 50, 20, 1, 1]
//
// Round 9: back to the round-2 fused single kernel (best measured: 89.8us,
// DRAM 55.5%, occ 51% vs ~87% theoretical). Changes vs that baseline:
//   1) 128-thread blocks, 2048 blocks  -> 16 concurrent blocks/SM, finer
//      tail granularity (R2's occupancy was schedule-limited, not resource-
//      limited).
//   2) unroll 10 on the field-2/3 token loops -> 50 E-loads front-batched
//      per thread (the load shape that measured 68.6% DRAM duty in R4).

#define B_TOTAL 16384
#define LAT 16

template<int SEQ, long DIM, int UNR>
__device__ __forceinline__ void do_field(const int* __restrict__ xp,
                                         const float* __restrict__ E,
                                         const float* __restrict__ L,
                                         int lane, float wsc,
                                         float (&acc)[5], float& lin0, float& lin1)
{
#pragma unroll UNR
    for (int t = 0; t < SEQ; ++t) {
        const int tok = __ldg(xp + t);
        const float* e = E + (size_t)tok * LAT + lane;
        acc[0] += __ldg(e);
        acc[1] += __ldg(e + DIM * LAT);
        acc[2] += __ldg(e + DIM * LAT * 2);
        acc[3] += __ldg(e + DIM * LAT * 3);
        acc[4] += __ldg(e + DIM * LAT * 4);
        // all 16 lanes same address -> single broadcast request
        if (t & 1) lin1 += __ldg(L + tok) * wsc;
        else       lin0 += __ldg(L + tok) * wsc;
    }
}

__global__ __launch_bounds__(128) void ffm_kernel(
    const int* __restrict__ x0, const int* __restrict__ x1, const int* __restrict__ x2,
    const int* __restrict__ x3, const int* __restrict__ x4, const int* __restrict__ x5,
    const float* __restrict__ E0, const float* __restrict__ E1, const float* __restrict__ E2,
    const float* __restrict__ E3, const float* __restrict__ E4, const float* __restrict__ E5,
    const float* __restrict__ L0, const float* __restrict__ L1, const float* __restrict__ L2,
    const float* __restrict__ L3, const float* __restrict__ L4, const float* __restrict__ L5,
    const float* __restrict__ Wd, const float* __restrict__ bd,
    float* __restrict__ out)
{
    const int tid  = blockIdx.x * blockDim.x + threadIdx.x;
    const int b    = tid >> 4;           // one batch element per 16 lanes
    const int lane = threadIdx.x & 15;   // lane = latent dim
    if (b >= B_TOTAL) return;

    float a0[5] = {0,0,0,0,0};
    float a1[5] = {0,0,0,0,0};
    float a2[5] = {0,0,0,0,0};
    float a3[5] = {0,0,0,0,0};
    float a4[5] = {0,0,0,0,0};
    float a5[5] = {0,0,0,0,0};
    float lin0 = 0.f, lin1 = 0.f;

    const float w0 = __ldg(Wd + 0);
    const float w1 = __ldg(Wd + 1);
    const float w2 = __ldg(Wd + 2) * (1.0f / 50.0f);
    const float w3 = __ldg(Wd + 3) * (1.0f / 20.0f);
    const float w4 = __ldg(Wd + 4);
    const float w5 = __ldg(Wd + 5);

    do_field<1,  1000000, 1 >(x0 + (size_t)b * 1,  E0, L0, lane, w0, a0, lin0, lin1);
    do_field<1,   500000, 1 >(x1 + (size_t)b * 1,  E1, L1, lane, w1, a1, lin0, lin1);
    do_field<50,  500000, 10>(x2 + (size_t)b * 50, E2, L2, lane, w2, a2, lin0, lin1);
    do_field<20,  100000, 10>(x3 + (size_t)b * 20, E3, L3, lane, w3, a3, lin0, lin1);
    do_field<1,    10000, 1 >(x4 + (size_t)b * 1,  E4, L4, lane, w4, a4, lin0, lin1);
    do_field<1,     1000, 1 >(x5 + (size_t)b * 1,  E5, L5, lane, w5, a5, lin0, lin1);

    const float lin = lin0 + lin1;

    // means: fields 0,1,4,5 have seq=1 (no scale needed)
#pragma unroll
    for (int k = 0; k < 5; ++k) a2[k] *= (1.0f / 50.0f);
#pragma unroll
    for (int k = 0; k < 5; ++k) a3[k] *= (1.0f / 20.0f);

    // fm = sum over pairs (i<j) of acc_i[j-1] * acc_j[i]
    float fm = 0.f;
    fm += a0[0]*a1[0];  // (0,1)
    fm += a0[1]*a2[0];  // (0,2)
    fm += a0[2]*a3[0];  // (0,3)
    fm += a0[3]*a4[0];  // (0,4)
    fm += a0[4]*a5[0];  // (0,5)
    fm += a1[1]*a2[1];  // (1,2)
    fm += a1[2]*a3[1];  // (1,3)
    fm += a1[3]*a4[1];  // (1,4)
    fm += a1[4]*a5[1];  // (1,5)
    fm += a2[2]*a3[2];  // (2,3)
    fm += a2[3]*a4[2];  // (2,4)
    fm += a2[4]*a5[2];  // (2,5)
    fm += a3[3]*a4[3];  // (3,4)
    fm += a3[4]*a5[3];  // (3,5)
    fm += a4[4]*a5[4];  // (4,5)

    // reduce fm over the 16 latent lanes
    fm += __shfl_xor_sync(0xffffffffu, fm, 8, 16);
    fm += __shfl_xor_sync(0xffffffffu, fm, 4, 16);
    fm += __shfl_xor_sync(0xffffffffu, fm, 2, 16);
    fm += __shfl_xor_sync(0xffffffffu, fm, 1, 16);

    if (lane == 0) {
        float z = lin + __ldg(bd);
        z = z > 0.f ? z : 0.f;      // relu
        z += fm;
        out[b] = 1.0f / (1.0f + expf(-z));
    }
}

extern "C" void kernel_launch(void* const* d_in, const int* in_sizes, int n_in,
                              void* d_out, int out_size)
{
    static const long DIMS[6] = {1000000, 500000, 500000, 100000, 10000, 1000};

    const int*   x[6];
    const float* E[6];
    const float* L[6];

    for (int i = 0; i < 6; ++i) x[i] = (const int*)d_in[i];

    // Inputs 6..17 are E and L tables in field order; disambiguate by size:
    // E_i has 80*DIMS[i] elements, L_i has DIMS[i]. Disjoint sets.
    int ei = 0, li = 0;
    for (int i = 6; i < 18 && i < n_in; ++i) {
        long sz = (long)in_sizes[i];
        if (ei < 6 && sz == 80L * DIMS[ei]) {
            E[ei++] = (const float*)d_in[i];
        } else {
            L[li++] = (const float*)d_in[i];
        }
    }

    const float* Wd = (const float*)d_in[18];
    const float* bd = (const float*)d_in[19];

    const int threads = 128;                       // 8 elems/block
    const int blocks  = (B_TOTAL * 16) / threads;  // 2048 blocks

    ffm_kernel<<<blocks, threads>>>(
        x[0], x[1], x[2], x[3], x[4], x[5],
        E[0], E[1], E[2], E[3], E[4], E[5],
        L[0], L[1], L[2], L[3], L[4], L[5],
        Wd, bd, (float*)d_out);
}